// round 3
// baseline (speedup 1.0000x reference)
#include <cuda_runtime.h>
#include <cuda_bf16.h>
#include <math.h>

#define N_NODES 100000
#define E_EDGES 3200000
#define TOT_E   (E_EDGES + N_NODES)   // edges + self loops = 3,300,000
#define IN_DIM  512
#define HID     256
#define NC      40
#define SCAN_B  1024
#define NBLK    ((N_NODES + SCAN_B - 1) / SCAN_B)   // 98

// ---------------- scratch (device globals; no allocations allowed) ----------
__device__ int   g_degcnt[N_NODES];
__device__ int   g_colcnt[N_NODES];
__device__ int   g_colptr[N_NODES + 1];
__device__ int   g_cur[N_NODES];
__device__ float g_dis[N_NODES];
__device__ int   g_rows[TOT_E];
__device__ float g_norms[TOT_E];
__device__ float g_B0[(size_t)N_NODES * NC];
__device__ float g_B1[(size_t)N_NODES * NC];
__device__ float g_h[(size_t)N_NODES * HID];
__device__ int   g_bsum[NBLK + 2];
__device__ int   g_ei64;    // 1 if edge_index stored as int64, 0 if int32
__device__ int   g_mask32;  // 1 if train_mask stored as int32, 0 if bool/byte

// ---------------- dtype detection (deterministic, graph-capturable) ---------
// int64 edge_index with values < 2^31: every odd 32-bit word is 0.
// int32 edge_index: odd words are random edge ids (P[all 256 samples==0] ~ 0).
// int32 mask: bytes at offset %4 != 0 are 0. bool mask: those bytes are ~50% 1.
__global__ void k_detect(const int* __restrict__ ei32,
                         const unsigned char* __restrict__ mask) {
    __shared__ int s_ei_nz, s_mask_nz;
    int t = threadIdx.x;
    if (t == 0) { s_ei_nz = 0; s_mask_nz = 0; }
    __syncthreads();
    int eidx = (t * 12347 + 5) % E_EDGES;          // sample odd word of pair
    if (ei32[2 * eidx + 1] != 0) atomicOr(&s_ei_nz, 1);
    int midx = (t * 97 + 1) % (N_NODES / 4);
    if (mask[4 * midx + 1] != 0) atomicOr(&s_mask_nz, 1);
    __syncthreads();
    if (t == 0) {
        g_ei64 = (s_ei_nz == 0) ? 1 : 0;
        g_mask32 = (s_mask_nz == 0) ? 1 : 0;
    }
}

__device__ __forceinline__ void load_edge(const void* ei, int i, int& r, int& c) {
    if (g_ei64) {
        const long long* p = (const long long*)ei;
        r = (int)p[i];
        c = (int)p[(size_t)E_EDGES + i];
    } else {
        const int* p = (const int*)ei;
        r = p[i];
        c = p[(size_t)E_EDGES + i];
    }
}

__device__ __forceinline__ bool load_mask(const void* mask, int v) {
    if (g_mask32) return ((const int*)mask)[v] != 0;
    return ((const unsigned char*)mask)[v] != 0;
}

// ---------------- setup kernels ---------------------------------------------
__global__ void k_init() {
    int i = blockIdx.x * blockDim.x + threadIdx.x;
    if (i < N_NODES) {
        g_degcnt[i] = 1;   // self loop pre-counted
        g_colcnt[i] = 1;   // self loop pre-counted
    }
}

__global__ void k_hist(const void* __restrict__ ei) {
    int i = blockIdx.x * blockDim.x + threadIdx.x;
    if (i < E_EDGES) {
        int r, c;
        load_edge(ei, i, r, c);
        atomicAdd(&g_degcnt[r], 1);
        atomicAdd(&g_colcnt[c], 1);
    }
}

__global__ void k_dis() {
    int i = blockIdx.x * blockDim.x + threadIdx.x;
    if (i < N_NODES) g_dis[i] = rsqrtf((float)g_degcnt[i]);
}

// exclusive scan of g_colcnt -> g_colptr (3 stages)
__global__ void k_scan1() {
    __shared__ int s[SCAN_B];
    int t = threadIdx.x;
    int gid = blockIdx.x * SCAN_B + t;
    int v = (gid < N_NODES) ? g_colcnt[gid] : 0;
    s[t] = v;
    __syncthreads();
    for (int off = 1; off < SCAN_B; off <<= 1) {
        int tmp = (t >= off) ? s[t - off] : 0;
        __syncthreads();
        s[t] += tmp;
        __syncthreads();
    }
    if (gid < N_NODES) g_colptr[gid] = s[t] - v;      // exclusive within block
    if (t == SCAN_B - 1) g_bsum[blockIdx.x] = s[t];   // block total
}

__global__ void k_scan2() {  // 128 threads, NBLK=98 <= 128
    __shared__ int s[128];
    int t = threadIdx.x;
    int v = (t < NBLK) ? g_bsum[t] : 0;
    s[t] = v;
    __syncthreads();
    for (int off = 1; off < 128; off <<= 1) {
        int tmp = (t >= off) ? s[t - off] : 0;
        __syncthreads();
        s[t] += tmp;
        __syncthreads();
    }
    if (t < NBLK) g_bsum[t] = s[t] - v;               // exclusive
    if (t == NBLK - 1) g_bsum[NBLK] = s[t];           // grand total = TOT_E
}

__global__ void k_scan3() {
    int gid = blockIdx.x * SCAN_B + threadIdx.x;
    if (gid < N_NODES) {
        int v = g_colptr[gid] + g_bsum[blockIdx.x];
        g_colptr[gid] = v;
        g_cur[gid] = v;
    }
    if (blockIdx.x == 0 && threadIdx.x == 0) g_colptr[N_NODES] = g_bsum[NBLK];
}

__global__ void k_fill(const void* __restrict__ ei) {
    int i = blockIdx.x * blockDim.x + threadIdx.x;
    if (i >= TOT_E) return;
    int r, c;
    if (i < E_EDGES) {
        load_edge(ei, i, r, c);
    } else {
        r = c = i - E_EDGES;   // self loop
    }
    float nm = g_dis[r] * g_dis[c];
    int pos = atomicAdd(&g_cur[c], 1);
    g_rows[pos] = r;
    g_norms[pos] = nm;
}

// ---------------- GEMM1: g_h = relu(X @ W1^T + b1) ---------------------------
// X[M,512], W1[256,512], H[M,256].  128x128 tile, BK=16, 8x8 per thread.
__global__ __launch_bounds__(256, 2)
void k_gemm1(const float* __restrict__ X, const float* __restrict__ W1,
             const float* __restrict__ b1) {
    const int BM = 128, BN = 128, BK = 16;
    __shared__ float As[BK][BM];
    __shared__ float Bs[BK][BN];
    int tid = threadIdx.x;
    int m0 = blockIdx.x * BM;
    int n0 = blockIdx.y * BN;
    int tx = tid & 15, ty = tid >> 4;

    float acc[8][8];
#pragma unroll
    for (int i = 0; i < 8; i++)
#pragma unroll
        for (int j = 0; j < 8; j++) acc[i][j] = 0.f;

    for (int k0 = 0; k0 < IN_DIM; k0 += BK) {
#pragma unroll
        for (int i = 0; i < 2; ++i) {
            int slot = tid + 256 * i;       // 0..511 float4 slots
            int m = slot >> 2;
            int kk = (slot & 3) << 2;
            int gm = m0 + m;
            float4 v = make_float4(0.f, 0.f, 0.f, 0.f);
            if (gm < N_NODES)
                v = *(const float4*)(X + (size_t)gm * IN_DIM + k0 + kk);
            As[kk + 0][m] = v.x; As[kk + 1][m] = v.y;
            As[kk + 2][m] = v.z; As[kk + 3][m] = v.w;
        }
#pragma unroll
        for (int i = 0; i < 2; ++i) {
            int slot = tid + 256 * i;
            int n = slot >> 2;
            int kk = (slot & 3) << 2;
            float4 v = *(const float4*)(W1 + (size_t)(n0 + n) * IN_DIM + k0 + kk);
            Bs[kk + 0][n] = v.x; Bs[kk + 1][n] = v.y;
            Bs[kk + 2][n] = v.z; Bs[kk + 3][n] = v.w;
        }
        __syncthreads();
#pragma unroll
        for (int k = 0; k < BK; ++k) {
            float4 a0 = *(const float4*)&As[k][ty * 8];
            float4 a1 = *(const float4*)&As[k][ty * 8 + 4];
            float4 b0 = *(const float4*)&Bs[k][tx * 8];
            float4 b1 = *(const float4*)&Bs[k][tx * 8 + 4];
            float ar[8] = {a0.x, a0.y, a0.z, a0.w, a1.x, a1.y, a1.z, a1.w};
            float br[8] = {b0.x, b0.y, b0.z, b0.w, b1.x, b1.y, b1.z, b1.w};
#pragma unroll
            for (int i = 0; i < 8; i++)
#pragma unroll
                for (int j = 0; j < 8; j++) acc[i][j] += ar[i] * br[j];
        }
        __syncthreads();
    }
#pragma unroll
    for (int i = 0; i < 8; i++) {
        int gm = m0 + ty * 8 + i;
        if (gm >= N_NODES) continue;
#pragma unroll
        for (int j = 0; j < 8; j++) {
            int gn = n0 + tx * 8 + j;
            float v = acc[i][j] + b1[gn];
            g_h[(size_t)gm * HID + gn] = fmaxf(v, 0.f);
        }
    }
}

// ---------------- PLP step: warp per destination node ------------------------
// step parity: odd -> dst=g_B1, even -> dst=g_B0. src: step1=ext, else other buf.
__global__ __launch_bounds__(256)
void k_plp(const float* __restrict__ ext_src,
           const void* __restrict__ mask,
           const float* __restrict__ hard, int step) {
    int warp = (blockIdx.x * blockDim.x + threadIdx.x) >> 5;
    int lane = threadIdx.x & 31;
    if (warp >= N_NODES) return;
    int v = warp;

    const float* src = (step == 1) ? ext_src : ((step & 1) ? g_B0 : g_B1);
    float* dst = (step & 1) ? g_B1 : g_B0;

    if (load_mask(mask, v)) {
        if (step <= 2) {  // after step 2 both buffers already hold hard_one_hot
            dst[(size_t)v * NC + lane] = hard[(size_t)v * NC + lane];
            if (lane < 8)
                dst[(size_t)v * NC + 32 + lane] = hard[(size_t)v * NC + 32 + lane];
        }
        return;
    }

    int e = g_colptr[v];
    int end = g_colptr[v + 1];
    float a0 = 0.f, a1 = 0.f, c0 = 0.f, c1 = 0.f;
    for (; e + 2 <= end; e += 2) {
        int r0 = g_rows[e], r1 = g_rows[e + 1];
        float n0 = g_norms[e], n1 = g_norms[e + 1];
        const float* p0 = src + (size_t)r0 * NC;
        const float* p1 = src + (size_t)r1 * NC;
        a0 += n0 * p0[lane];
        c0 += n1 * p1[lane];
        if (lane < 8) {
            a1 += n0 * p0[32 + lane];
            c1 += n1 * p1[32 + lane];
        }
    }
    if (e < end) {
        int r0 = g_rows[e];
        float n0 = g_norms[e];
        const float* p0 = src + (size_t)r0 * NC;
        a0 += n0 * p0[lane];
        if (lane < 8) a1 += n0 * p0[32 + lane];
    }
    a0 += c0; a1 += c1;
    dst[(size_t)v * NC + lane] = a0;
    if (lane < 8) dst[(size_t)v * NC + 32 + lane] = a1;
}

// ---------------- FC2 + final combine ----------------------------------------
// out[n,c] = sig(alpha[n]) * plp[n,c] + (1-sig) * (g_h[n,:] . W2[c,:] + b2[c])
__global__ __launch_bounds__(320)
void k_final(const float* __restrict__ W2, const float* __restrict__ b2,
             const float* __restrict__ alpha, float* __restrict__ out) {
    __shared__ float sW[NC * HID];   // 40 KB
    int tid = threadIdx.x;
    for (int i = tid; i < (NC * HID) / 4; i += 320)
        ((float4*)sW)[i] = ((const float4*)W2)[i];
    __syncthreads();

    int node = blockIdx.x * 8 + tid / NC;
    int c = tid % NC;
    if (node >= N_NODES) return;

    const float4* hv = (const float4*)(g_h + (size_t)node * HID);
    const float4* wv = (const float4*)(sW + c * HID);
    float acc = 0.f;
#pragma unroll 8
    for (int k = 0; k < HID / 4; k++) {
        float4 a = hv[k];
        float4 b = wv[k];
        acc += a.x * b.x + a.y * b.y + a.z * b.z + a.w * b.w;
    }
    acc += b2[c];
    float a = 1.f / (1.f + expf(-alpha[node]));
    out[(size_t)node * NC + c] = a * g_B0[(size_t)node * NC + c] + (1.f - a) * acc;
}

// ---------------- launch ------------------------------------------------------
extern "C" void kernel_launch(void* const* d_in, const int* in_sizes, int n_in,
                              void* d_out, int out_size) {
    const float* x     = (const float*)d_in[0];
    const void*  ei    = d_in[1];
    const float* linit = (const float*)d_in[2];
    const void*  mask  = d_in[3];
    const float* hard  = (const float*)d_in[4];
    const float* w1    = (const float*)d_in[5];
    const float* b1    = (const float*)d_in[6];
    const float* w2    = (const float*)d_in[7];
    const float* b2    = (const float*)d_in[8];
    const float* alpha = (const float*)d_in[9];
    float*       out   = (float*)d_out;

    // dtype detection (edge_index int32 vs int64, mask bool vs int32)
    k_detect<<<1, 256>>>((const int*)ei, (const unsigned char*)mask);

    // CSC build
    k_init<<<(N_NODES + 255) / 256, 256>>>();
    k_hist<<<(E_EDGES + 255) / 256, 256>>>(ei);
    k_dis<<<(N_NODES + 255) / 256, 256>>>();
    k_scan1<<<NBLK, SCAN_B>>>();
    k_scan2<<<1, 128>>>();
    k_scan3<<<NBLK, SCAN_B>>>();
    k_fill<<<(TOT_E + 255) / 256, 256>>>(ei);

    // MLP layer 1 (independent of PLP)
    dim3 g1((N_NODES + 127) / 128, HID / 128);
    k_gemm1<<<g1, 256>>>(x, w1, b1);

    // 10 label-propagation steps (warp per node, pull mode, no atomics)
    int plp_blocks = (N_NODES * 32 + 255) / 256;
    for (int s = 1; s <= 10; ++s)
        k_plp<<<plp_blocks, 256>>>(linit, mask, hard, s);

    // FC2 + combine (reads g_B0 = plp after step 10)
    k_final<<<(N_NODES + 7) / 8, 320>>>(w2, b2, alpha, out);
}

// round 4
// speedup vs baseline: 1.0196x; 1.0196x over previous
#include <cuda_runtime.h>
#include <cuda_bf16.h>
#include <math.h>

#define N_NODES 100000
#define E_EDGES 3200000
#define TOT_E   (E_EDGES + N_NODES)   // edges + self loops = 3,300,000
#define IN_DIM  512
#define HID     256
#define NC      40
#define SCAN_B  1024
#define NBLK    ((N_NODES + SCAN_B - 1) / SCAN_B)   // 98

// ---------------- scratch (device globals; no allocations allowed) ----------
__device__ int   g_degcnt[N_NODES];
__device__ int   g_colcnt[N_NODES];
__device__ int   g_colptr[N_NODES + 1];
__device__ int   g_cur[N_NODES];
__device__ float g_dis[N_NODES];
__device__ int   g_rows[TOT_E];
__device__ float g_norms[TOT_E];
__device__ float g_B0[(size_t)N_NODES * NC];
__device__ float g_B1[(size_t)N_NODES * NC];
__device__ float g_h[(size_t)N_NODES * HID];
__device__ int   g_bsum[NBLK + 2];
__device__ int   g_ei64;    // 1 if edge_index stored as int64, 0 if int32
__device__ int   g_mask32;  // 1 if train_mask stored as int32, 0 if bool/byte

// ---------------- dtype detection (deterministic, graph-capturable) ---------
__global__ void k_detect(const int* __restrict__ ei32,
                         const unsigned char* __restrict__ mask) {
    __shared__ int s_ei_nz, s_mask_nz;
    int t = threadIdx.x;
    if (t == 0) { s_ei_nz = 0; s_mask_nz = 0; }
    __syncthreads();
    int eidx = (t * 12347 + 5) % E_EDGES;          // sample odd word of pair
    if (ei32[2 * eidx + 1] != 0) atomicOr(&s_ei_nz, 1);
    int midx = (t * 97 + 1) % (N_NODES / 4);
    if (mask[4 * midx + 1] != 0) atomicOr(&s_mask_nz, 1);
    __syncthreads();
    if (t == 0) {
        g_ei64 = (s_ei_nz == 0) ? 1 : 0;
        g_mask32 = (s_mask_nz == 0) ? 1 : 0;
    }
}

__device__ __forceinline__ void load_edge(const void* ei, int i, int& r, int& c) {
    if (g_ei64) {
        const long long* p = (const long long*)ei;
        r = (int)p[i];
        c = (int)p[(size_t)E_EDGES + i];
    } else {
        const int* p = (const int*)ei;
        r = p[i];
        c = p[(size_t)E_EDGES + i];
    }
}

__device__ __forceinline__ bool load_mask(const void* mask, int v) {
    if (g_mask32) return ((const int*)mask)[v] != 0;
    return ((const unsigned char*)mask)[v] != 0;
}

// ---------------- f32x2 packed-FMA helpers (sm_103a) --------------------------
__device__ __forceinline__ void ffma2(unsigned long long& acc,
                                      unsigned long long a,
                                      unsigned long long b) {
    asm("fma.rn.f32x2 %0, %1, %2, %3;" : "=l"(acc) : "l"(a), "l"(b), "l"(acc));
}
__device__ __forceinline__ unsigned long long dup2(float v) {
    unsigned long long r;
    asm("mov.b64 %0, {%1, %1};" : "=l"(r) : "f"(v));
    return r;
}

// ---------------- setup kernels ---------------------------------------------
__global__ void k_init(const void* __restrict__ mask) {
    int i = blockIdx.x * blockDim.x + threadIdx.x;
    if (i < N_NODES) {
        g_degcnt[i] = 1;                              // self loop counts in deg
        g_colcnt[i] = load_mask(mask, i) ? 0 : 1;     // CSC drops masked dst
    }
}

__global__ void k_hist(const void* __restrict__ ei, const void* __restrict__ mask) {
    int i = blockIdx.x * blockDim.x + threadIdx.x;
    if (i < E_EDGES) {
        int r, c;
        load_edge(ei, i, r, c);
        atomicAdd(&g_degcnt[r], 1);
        if (!load_mask(mask, c)) atomicAdd(&g_colcnt[c], 1);
    }
}

__global__ void k_dis() {
    int i = blockIdx.x * blockDim.x + threadIdx.x;
    if (i < N_NODES) g_dis[i] = rsqrtf((float)g_degcnt[i]);
}

// exclusive scan of g_colcnt -> g_colptr (3 stages)
__global__ void k_scan1() {
    __shared__ int s[SCAN_B];
    int t = threadIdx.x;
    int gid = blockIdx.x * SCAN_B + t;
    int v = (gid < N_NODES) ? g_colcnt[gid] : 0;
    s[t] = v;
    __syncthreads();
    for (int off = 1; off < SCAN_B; off <<= 1) {
        int tmp = (t >= off) ? s[t - off] : 0;
        __syncthreads();
        s[t] += tmp;
        __syncthreads();
    }
    if (gid < N_NODES) g_colptr[gid] = s[t] - v;      // exclusive within block
    if (t == SCAN_B - 1) g_bsum[blockIdx.x] = s[t];   // block total
}

__global__ void k_scan2() {  // 128 threads, NBLK=98 <= 128
    __shared__ int s[128];
    int t = threadIdx.x;
    int v = (t < NBLK) ? g_bsum[t] : 0;
    s[t] = v;
    __syncthreads();
    for (int off = 1; off < 128; off <<= 1) {
        int tmp = (t >= off) ? s[t - off] : 0;
        __syncthreads();
        s[t] += tmp;
        __syncthreads();
    }
    if (t < NBLK) g_bsum[t] = s[t] - v;               // exclusive
    if (t == NBLK - 1) g_bsum[NBLK] = s[t];           // grand total
}

__global__ void k_scan3() {
    int gid = blockIdx.x * SCAN_B + threadIdx.x;
    if (gid < N_NODES) {
        int v = g_colptr[gid] + g_bsum[blockIdx.x];
        g_colptr[gid] = v;
        g_cur[gid] = v;
    }
    if (blockIdx.x == 0 && threadIdx.x == 0) g_colptr[N_NODES] = g_bsum[NBLK];
}

__global__ void k_fill(const void* __restrict__ ei, const void* __restrict__ mask) {
    int i = blockIdx.x * blockDim.x + threadIdx.x;
    if (i >= TOT_E) return;
    int r, c;
    if (i < E_EDGES) {
        load_edge(ei, i, r, c);
    } else {
        r = c = i - E_EDGES;   // self loop
    }
    if (load_mask(mask, c)) return;   // masked destinations are never read
    float nm = g_dis[r] * g_dis[c];
    int pos = atomicAdd(&g_cur[c], 1);
    g_rows[pos] = r;
    g_norms[pos] = nm;
}

// ---------------- GEMM1: g_h = relu(X @ W1^T + b1) ---------------------------
// X[M,512], W1[256,512], H[M,256].  128x128 tile, BK=16, 8x8 per thread,
// inner product via packed fma.rn.f32x2 (2 FLOP per fma-pipe slot).
__global__ __launch_bounds__(256, 2)
void k_gemm1(const float* __restrict__ X, const float* __restrict__ W1,
             const float* __restrict__ b1) {
    const int BM = 128, BN = 128, BK = 16;
    __shared__ __align__(16) float As[BK][BM];
    __shared__ __align__(16) float Bs[BK][BN];
    int tid = threadIdx.x;
    int m0 = blockIdx.x * BM;
    int n0 = blockIdx.y * BN;
    int tx = tid & 15, ty = tid >> 4;

    // acc2[i][j2] = packed pair of classes (tx*8 + 2*j2, +1) for row ty*8+i
    unsigned long long acc2[8][4];
#pragma unroll
    for (int i = 0; i < 8; i++)
#pragma unroll
        for (int j = 0; j < 4; j++) acc2[i][j] = 0ull;

    for (int k0 = 0; k0 < IN_DIM; k0 += BK) {
#pragma unroll
        for (int i = 0; i < 2; ++i) {
            int slot = tid + 256 * i;       // 0..511 float4 slots
            int m = slot >> 2;
            int kk = (slot & 3) << 2;
            int gm = m0 + m;
            float4 v = make_float4(0.f, 0.f, 0.f, 0.f);
            if (gm < N_NODES)
                v = *(const float4*)(X + (size_t)gm * IN_DIM + k0 + kk);
            As[kk + 0][m] = v.x; As[kk + 1][m] = v.y;
            As[kk + 2][m] = v.z; As[kk + 3][m] = v.w;
        }
#pragma unroll
        for (int i = 0; i < 2; ++i) {
            int slot = tid + 256 * i;
            int n = slot >> 2;
            int kk = (slot & 3) << 2;
            float4 v = *(const float4*)(W1 + (size_t)(n0 + n) * IN_DIM + k0 + kk);
            Bs[kk + 0][n] = v.x; Bs[kk + 1][n] = v.y;
            Bs[kk + 2][n] = v.z; Bs[kk + 3][n] = v.w;
        }
        __syncthreads();
#pragma unroll
        for (int k = 0; k < BK; ++k) {
            float4 a0 = *(const float4*)&As[k][ty * 8];
            float4 a1 = *(const float4*)&As[k][ty * 8 + 4];
            // B pairs directly as 64-bit packed lanes (16B-aligned rows)
            ulonglong2 bq0 = *(const ulonglong2*)&Bs[k][tx * 8];
            ulonglong2 bq1 = *(const ulonglong2*)&Bs[k][tx * 8 + 4];
            unsigned long long br2[4] = {bq0.x, bq0.y, bq1.x, bq1.y};
            float ar[8] = {a0.x, a0.y, a0.z, a0.w, a1.x, a1.y, a1.z, a1.w};
#pragma unroll
            for (int i = 0; i < 8; i++) {
                unsigned long long ad = dup2(ar[i]);
#pragma unroll
                for (int j = 0; j < 4; j++) ffma2(acc2[i][j], ad, br2[j]);
            }
        }
        __syncthreads();
    }
#pragma unroll
    for (int i = 0; i < 8; i++) {
        int gm = m0 + ty * 8 + i;
        if (gm >= N_NODES) continue;
#pragma unroll
        for (int j = 0; j < 4; j++) {
            float2 p = *reinterpret_cast<float2*>(&acc2[i][j]);
            int gn = n0 + tx * 8 + 2 * j;
            g_h[(size_t)gm * HID + gn]     = fmaxf(p.x + b1[gn], 0.f);
            g_h[(size_t)gm * HID + gn + 1] = fmaxf(p.y + b1[gn + 1], 0.f);
        }
    }
}

// ---------------- PLP step: warp per destination node ------------------------
__global__ __launch_bounds__(256)
void k_plp(const float* __restrict__ ext_src,
           const void* __restrict__ mask,
           const float* __restrict__ hard, int step) {
    int warp = (blockIdx.x * blockDim.x + threadIdx.x) >> 5;
    int lane = threadIdx.x & 31;
    if (warp >= N_NODES) return;
    int v = warp;

    const float* src = (step == 1) ? ext_src : ((step & 1) ? g_B0 : g_B1);
    float* dst = (step & 1) ? g_B1 : g_B0;

    if (load_mask(mask, v)) {
        if (step <= 2) {  // after step 2 both buffers already hold hard rows
            dst[(size_t)v * NC + lane] = hard[(size_t)v * NC + lane];
            if (lane < 8)
                dst[(size_t)v * NC + 32 + lane] = hard[(size_t)v * NC + 32 + lane];
        }
        return;
    }

    int e = g_colptr[v];
    int end = g_colptr[v + 1];
    float a0 = 0.f, a1 = 0.f, c0 = 0.f, c1 = 0.f;
    for (; e + 2 <= end; e += 2) {
        int r0 = g_rows[e], r1 = g_rows[e + 1];
        float n0 = g_norms[e], n1 = g_norms[e + 1];
        const float* p0 = src + (size_t)r0 * NC;
        const float* p1 = src + (size_t)r1 * NC;
        a0 += n0 * p0[lane];
        c0 += n1 * p1[lane];
        if (lane < 8) {
            a1 += n0 * p0[32 + lane];
            c1 += n1 * p1[32 + lane];
        }
    }
    if (e < end) {
        int r0 = g_rows[e];
        float n0 = g_norms[e];
        const float* p0 = src + (size_t)r0 * NC;
        a0 += n0 * p0[lane];
        if (lane < 8) a1 += n0 * p0[32 + lane];
    }
    a0 += c0; a1 += c1;
    dst[(size_t)v * NC + lane] = a0;
    if (lane < 8) dst[(size_t)v * NC + 32 + lane] = a1;
}

// ---------------- FC2 + final combine ----------------------------------------
__global__ __launch_bounds__(320)
void k_final(const float* __restrict__ W2, const float* __restrict__ b2,
             const float* __restrict__ alpha, float* __restrict__ out) {
    __shared__ float sW[NC * HID];   // 40 KB
    int tid = threadIdx.x;
    for (int i = tid; i < (NC * HID) / 4; i += 320)
        ((float4*)sW)[i] = ((const float4*)W2)[i];
    __syncthreads();

    int node = blockIdx.x * 8 + tid / NC;
    int c = tid % NC;
    if (node >= N_NODES) return;

    const float4* hv = (const float4*)(g_h + (size_t)node * HID);
    const float4* wv = (const float4*)(sW + c * HID);
    float acc = 0.f;
#pragma unroll 8
    for (int k = 0; k < HID / 4; k++) {
        float4 a = hv[k];
        float4 b = wv[k];
        acc += a.x * b.x + a.y * b.y + a.z * b.z + a.w * b.w;
    }
    acc += b2[c];
    float a = 1.f / (1.f + expf(-alpha[node]));
    out[(size_t)node * NC + c] = a * g_B0[(size_t)node * NC + c] + (1.f - a) * acc;
}

// ---------------- launch ------------------------------------------------------
extern "C" void kernel_launch(void* const* d_in, const int* in_sizes, int n_in,
                              void* d_out, int out_size) {
    const float* x     = (const float*)d_in[0];
    const void*  ei    = d_in[1];
    const float* linit = (const float*)d_in[2];
    const void*  mask  = d_in[3];
    const float* hard  = (const float*)d_in[4];
    const float* w1    = (const float*)d_in[5];
    const float* b1    = (const float*)d_in[6];
    const float* w2    = (const float*)d_in[7];
    const float* b2    = (const float*)d_in[8];
    const float* alpha = (const float*)d_in[9];
    float*       out   = (float*)d_out;

    // dtype detection (edge_index int32 vs int64, mask bool vs int32)
    k_detect<<<1, 256>>>((const int*)ei, (const unsigned char*)mask);

    // CSC build (drops edges into masked destinations — never read by PLP)
    k_init<<<(N_NODES + 255) / 256, 256>>>(mask);
    k_hist<<<(E_EDGES + 255) / 256, 256>>>(ei, mask);
    k_dis<<<(N_NODES + 255) / 256, 256>>>();
    k_scan1<<<NBLK, SCAN_B>>>();
    k_scan2<<<1, 128>>>();
    k_scan3<<<NBLK, SCAN_B>>>();
    k_fill<<<(TOT_E + 255) / 256, 256>>>(ei, mask);

    // MLP layer 1 (independent of PLP)
    dim3 g1((N_NODES + 127) / 128, HID / 128);
    k_gemm1<<<g1, 256>>>(x, w1, b1);

    // 10 label-propagation steps (warp per node, pull mode, no atomics)
    int plp_blocks = (N_NODES * 32 + 255) / 256;
    for (int s = 1; s <= 10; ++s)
        k_plp<<<plp_blocks, 256>>>(linit, mask, hard, s);

    // FC2 + combine (reads g_B0 = plp after step 10)
    k_final<<<(N_NODES + 7) / 8, 320>>>(w2, b2, alpha, out);
}

// round 5
// speedup vs baseline: 1.0341x; 1.0142x over previous
#include <cuda_runtime.h>
#include <cuda_fp16.h>
#include <math.h>

#define N_NODES 100000
#define E_EDGES 3200000
#define TOT_E   (E_EDGES + N_NODES)   // edges + self loops = 3,300,000
#define IN_DIM  512
#define HID     256
#define NC      40
#define NC2     (NC / 2)              // 20 half2 words per row
#define SCAN_B  1024
#define NBLK    ((N_NODES + SCAN_B - 1) / SCAN_B)   // 98

// ---------------- scratch (device globals; no allocations allowed) ----------
__device__ int     g_degcnt[N_NODES];
__device__ int     g_colcnt[N_NODES];
__device__ int     g_colptr[N_NODES + 1];
__device__ int     g_cur[N_NODES];
__device__ float   g_dis[N_NODES];
__device__ int     g_rows[TOT_E];
__device__ float   g_norms[TOT_E];
__device__ __half2 g_B0h[(size_t)N_NODES * NC2];
__device__ __half2 g_B1h[(size_t)N_NODES * NC2];
__device__ float   g_h[(size_t)N_NODES * HID];
__device__ int     g_bsum[NBLK + 2];
__device__ int     g_ei64;    // 1 if edge_index stored as int64, 0 if int32
__device__ int     g_mask32;  // 1 if train_mask stored as int32, 0 if bool/byte

// ---------------- dtype detection (deterministic, graph-capturable) ---------
__global__ void k_detect(const int* __restrict__ ei32,
                         const unsigned char* __restrict__ mask) {
    __shared__ int s_ei_nz, s_mask_nz;
    int t = threadIdx.x;
    if (t == 0) { s_ei_nz = 0; s_mask_nz = 0; }
    __syncthreads();
    int eidx = (t * 12347 + 5) % E_EDGES;          // sample odd word of pair
    if (ei32[2 * eidx + 1] != 0) atomicOr(&s_ei_nz, 1);
    int midx = (t * 97 + 1) % (N_NODES / 4);
    if (mask[4 * midx + 1] != 0) atomicOr(&s_mask_nz, 1);
    __syncthreads();
    if (t == 0) {
        g_ei64 = (s_ei_nz == 0) ? 1 : 0;
        g_mask32 = (s_mask_nz == 0) ? 1 : 0;
    }
}

__device__ __forceinline__ void load_edge(const void* ei, int i, int& r, int& c) {
    if (g_ei64) {
        const long long* p = (const long long*)ei;
        r = (int)p[i];
        c = (int)p[(size_t)E_EDGES + i];
    } else {
        const int* p = (const int*)ei;
        r = p[i];
        c = p[(size_t)E_EDGES + i];
    }
}

__device__ __forceinline__ bool load_mask(const void* mask, int v) {
    if (g_mask32) return ((const int*)mask)[v] != 0;
    return ((const unsigned char*)mask)[v] != 0;
}

// ---------------- f32x2 packed-FMA helpers (sm_103a) --------------------------
__device__ __forceinline__ void ffma2(unsigned long long& acc,
                                      unsigned long long a,
                                      unsigned long long b) {
    asm("fma.rn.f32x2 %0, %1, %2, %3;" : "=l"(acc) : "l"(a), "l"(b), "l"(acc));
}
__device__ __forceinline__ unsigned long long dup2(float v) {
    unsigned long long r;
    asm("mov.b64 %0, {%1, %1};" : "=l"(r) : "f"(v));
    return r;
}

// ---------------- setup kernels ---------------------------------------------
__global__ void k_init(const void* __restrict__ mask) {
    int i = blockIdx.x * blockDim.x + threadIdx.x;
    if (i < N_NODES) {
        g_degcnt[i] = 1;                              // self loop counts in deg
        g_colcnt[i] = load_mask(mask, i) ? 0 : 1;     // CSC drops masked dst
    }
}

__global__ void k_hist(const void* __restrict__ ei, const void* __restrict__ mask) {
    int i = blockIdx.x * blockDim.x + threadIdx.x;
    if (i < E_EDGES) {
        int r, c;
        load_edge(ei, i, r, c);
        atomicAdd(&g_degcnt[r], 1);
        if (!load_mask(mask, c)) atomicAdd(&g_colcnt[c], 1);
    }
}

__global__ void k_dis() {
    int i = blockIdx.x * blockDim.x + threadIdx.x;
    if (i < N_NODES) g_dis[i] = rsqrtf((float)g_degcnt[i]);
}

// exclusive scan of g_colcnt -> g_colptr (3 stages)
__global__ void k_scan1() {
    __shared__ int s[SCAN_B];
    int t = threadIdx.x;
    int gid = blockIdx.x * SCAN_B + t;
    int v = (gid < N_NODES) ? g_colcnt[gid] : 0;
    s[t] = v;
    __syncthreads();
    for (int off = 1; off < SCAN_B; off <<= 1) {
        int tmp = (t >= off) ? s[t - off] : 0;
        __syncthreads();
        s[t] += tmp;
        __syncthreads();
    }
    if (gid < N_NODES) g_colptr[gid] = s[t] - v;      // exclusive within block
    if (t == SCAN_B - 1) g_bsum[blockIdx.x] = s[t];   // block total
}

__global__ void k_scan2() {  // 128 threads, NBLK=98 <= 128
    __shared__ int s[128];
    int t = threadIdx.x;
    int v = (t < NBLK) ? g_bsum[t] : 0;
    s[t] = v;
    __syncthreads();
    for (int off = 1; off < 128; off <<= 1) {
        int tmp = (t >= off) ? s[t - off] : 0;
        __syncthreads();
        s[t] += tmp;
        __syncthreads();
    }
    if (t < NBLK) g_bsum[t] = s[t] - v;               // exclusive
    if (t == NBLK - 1) g_bsum[NBLK] = s[t];           // grand total
}

__global__ void k_scan3() {
    int gid = blockIdx.x * SCAN_B + threadIdx.x;
    if (gid < N_NODES) {
        int v = g_colptr[gid] + g_bsum[blockIdx.x];
        g_colptr[gid] = v;
        g_cur[gid] = v;
    }
    if (blockIdx.x == 0 && threadIdx.x == 0) g_colptr[N_NODES] = g_bsum[NBLK];
}

__global__ void k_fill(const void* __restrict__ ei, const void* __restrict__ mask) {
    int i = blockIdx.x * blockDim.x + threadIdx.x;
    if (i >= TOT_E) return;
    int r, c;
    if (i < E_EDGES) {
        load_edge(ei, i, r, c);
    } else {
        r = c = i - E_EDGES;   // self loop
    }
    if (load_mask(mask, c)) return;   // masked destinations are never read
    float nm = g_dis[r] * g_dis[c];
    int pos = atomicAdd(&g_cur[c], 1);
    g_rows[pos] = r;
    g_norms[pos] = nm;
}

// ---------------- GEMM1: g_h = relu(X @ W1^T + b1) ---------------------------
__global__ __launch_bounds__(256, 2)
void k_gemm1(const float* __restrict__ X, const float* __restrict__ W1,
             const float* __restrict__ b1) {
    const int BM = 128, BN = 128, BK = 16;
    __shared__ __align__(16) float As[BK][BM];
    __shared__ __align__(16) float Bs[BK][BN];
    int tid = threadIdx.x;
    int m0 = blockIdx.x * BM;
    int n0 = blockIdx.y * BN;
    int tx = tid & 15, ty = tid >> 4;

    unsigned long long acc2[8][4];
#pragma unroll
    for (int i = 0; i < 8; i++)
#pragma unroll
        for (int j = 0; j < 4; j++) acc2[i][j] = 0ull;

    for (int k0 = 0; k0 < IN_DIM; k0 += BK) {
#pragma unroll
        for (int i = 0; i < 2; ++i) {
            int slot = tid + 256 * i;       // 0..511 float4 slots
            int m = slot >> 2;
            int kk = (slot & 3) << 2;
            int gm = m0 + m;
            float4 v = make_float4(0.f, 0.f, 0.f, 0.f);
            if (gm < N_NODES)
                v = *(const float4*)(X + (size_t)gm * IN_DIM + k0 + kk);
            As[kk + 0][m] = v.x; As[kk + 1][m] = v.y;
            As[kk + 2][m] = v.z; As[kk + 3][m] = v.w;
        }
#pragma unroll
        for (int i = 0; i < 2; ++i) {
            int slot = tid + 256 * i;
            int n = slot >> 2;
            int kk = (slot & 3) << 2;
            float4 v = *(const float4*)(W1 + (size_t)(n0 + n) * IN_DIM + k0 + kk);
            Bs[kk + 0][n] = v.x; Bs[kk + 1][n] = v.y;
            Bs[kk + 2][n] = v.z; Bs[kk + 3][n] = v.w;
        }
        __syncthreads();
#pragma unroll
        for (int k = 0; k < BK; ++k) {
            float4 a0 = *(const float4*)&As[k][ty * 8];
            float4 a1 = *(const float4*)&As[k][ty * 8 + 4];
            ulonglong2 bq0 = *(const ulonglong2*)&Bs[k][tx * 8];
            ulonglong2 bq1 = *(const ulonglong2*)&Bs[k][tx * 8 + 4];
            unsigned long long br2[4] = {bq0.x, bq0.y, bq1.x, bq1.y};
            float ar[8] = {a0.x, a0.y, a0.z, a0.w, a1.x, a1.y, a1.z, a1.w};
#pragma unroll
            for (int i = 0; i < 8; i++) {
                unsigned long long ad = dup2(ar[i]);
#pragma unroll
                for (int j = 0; j < 4; j++) ffma2(acc2[i][j], ad, br2[j]);
            }
        }
        __syncthreads();
    }
#pragma unroll
    for (int i = 0; i < 8; i++) {
        int gm = m0 + ty * 8 + i;
        if (gm >= N_NODES) continue;
#pragma unroll
        for (int j = 0; j < 4; j++) {
            float2 p = *reinterpret_cast<float2*>(&acc2[i][j]);
            int gn = n0 + tx * 8 + 2 * j;
            g_h[(size_t)gm * HID + gn]     = fmaxf(p.x + b1[gn], 0.f);
            g_h[(size_t)gm * HID + gn + 1] = fmaxf(p.y + b1[gn + 1], 0.f);
        }
    }
}

// ---------------- PLP step: warp per destination node, fp16 buffers ----------
// 20 active lanes, 2 classes per lane (half2). Accumulate fp32, store half2.
__global__ __launch_bounds__(256)
void k_plp(const float* __restrict__ ext_src,
           const void* __restrict__ mask,
           const float* __restrict__ hard, int step) {
    int warp = (blockIdx.x * blockDim.x + threadIdx.x) >> 5;
    int lane = threadIdx.x & 31;
    if (warp >= N_NODES || lane >= NC2) return;
    int v = warp;

    __half2* dst = (step & 1) ? g_B1h : g_B0h;

    if (load_mask(mask, v)) {
        if (step <= 2) {  // afterwards both buffers already hold hard rows
            float2 hv = ((const float2*)hard)[(size_t)v * NC2 + lane];
            dst[(size_t)v * NC2 + lane] = __float22half2_rn(hv);
        }
        return;
    }

    int e = g_colptr[v];
    int end = g_colptr[v + 1];
    float ax = 0.f, ay = 0.f;

    if (step == 1) {   // source = external fp32 label_init
        for (; e + 2 <= end; e += 2) {
            int r0 = g_rows[e], r1 = g_rows[e + 1];
            float n0 = g_norms[e], n1 = g_norms[e + 1];
            float2 s0 = ((const float2*)ext_src)[(size_t)r0 * NC2 + lane];
            float2 s1 = ((const float2*)ext_src)[(size_t)r1 * NC2 + lane];
            ax += n0 * s0.x + n1 * s1.x;
            ay += n0 * s0.y + n1 * s1.y;
        }
        if (e < end) {
            int r0 = g_rows[e];
            float n0 = g_norms[e];
            float2 s0 = ((const float2*)ext_src)[(size_t)r0 * NC2 + lane];
            ax += n0 * s0.x;
            ay += n0 * s0.y;
        }
    } else {           // source = fp16 ping-pong buffer
        const __half2* src = (step & 1) ? g_B0h : g_B1h;
        for (; e + 4 <= end; e += 4) {
            int r0 = g_rows[e],     r1 = g_rows[e + 1];
            int r2 = g_rows[e + 2], r3 = g_rows[e + 3];
            float n0 = g_norms[e],     n1 = g_norms[e + 1];
            float n2 = g_norms[e + 2], n3 = g_norms[e + 3];
            float2 s0 = __half22float2(src[(size_t)r0 * NC2 + lane]);
            float2 s1 = __half22float2(src[(size_t)r1 * NC2 + lane]);
            float2 s2 = __half22float2(src[(size_t)r2 * NC2 + lane]);
            float2 s3 = __half22float2(src[(size_t)r3 * NC2 + lane]);
            ax += n0 * s0.x + n1 * s1.x + n2 * s2.x + n3 * s3.x;
            ay += n0 * s0.y + n1 * s1.y + n2 * s2.y + n3 * s3.y;
        }
        for (; e < end; ++e) {
            int r0 = g_rows[e];
            float n0 = g_norms[e];
            float2 s0 = __half22float2(src[(size_t)r0 * NC2 + lane]);
            ax += n0 * s0.x;
            ay += n0 * s0.y;
        }
    }
    dst[(size_t)v * NC2 + lane] = __float22half2_rn(make_float2(ax, ay));
}

// ---------------- FC2 + final combine ----------------------------------------
__global__ __launch_bounds__(320)
void k_final(const float* __restrict__ W2, const float* __restrict__ b2,
             const float* __restrict__ alpha, float* __restrict__ out) {
    __shared__ float sW[NC * HID];   // 40 KB
    int tid = threadIdx.x;
    for (int i = tid; i < (NC * HID) / 4; i += 320)
        ((float4*)sW)[i] = ((const float4*)W2)[i];
    __syncthreads();

    int node = blockIdx.x * 8 + tid / NC;
    int c = tid % NC;
    if (node >= N_NODES) return;

    const float4* hv = (const float4*)(g_h + (size_t)node * HID);
    const float4* wv = (const float4*)(sW + c * HID);
    float acc = 0.f;
#pragma unroll 8
    for (int k = 0; k < HID / 4; k++) {
        float4 a = hv[k];
        float4 b = wv[k];
        acc += a.x * b.x + a.y * b.y + a.z * b.z + a.w * b.w;
    }
    acc += b2[c];
    float a = 1.f / (1.f + expf(-alpha[node]));
    __half2 hw = g_B0h[(size_t)node * NC2 + (c >> 1)];
    float plpv = (c & 1) ? __high2float(hw) : __low2float(hw);
    out[(size_t)node * NC + c] = a * plpv + (1.f - a) * acc;
}

// ---------------- launch ------------------------------------------------------
extern "C" void kernel_launch(void* const* d_in, const int* in_sizes, int n_in,
                              void* d_out, int out_size) {
    const float* x     = (const float*)d_in[0];
    const void*  ei    = d_in[1];
    const float* linit = (const float*)d_in[2];
    const void*  mask  = d_in[3];
    const float* hard  = (const float*)d_in[4];
    const float* w1    = (const float*)d_in[5];
    const float* b1    = (const float*)d_in[6];
    const float* w2    = (const float*)d_in[7];
    const float* b2    = (const float*)d_in[8];
    const float* alpha = (const float*)d_in[9];
    float*       out   = (float*)d_out;

    // dtype detection (edge_index int32 vs int64, mask bool vs int32)
    k_detect<<<1, 256>>>((const int*)ei, (const unsigned char*)mask);

    // CSC build; k_gemm1 placed 4th so the ncu -s5-c1 window profiles it
    k_init<<<(N_NODES + 255) / 256, 256>>>(mask);
    k_hist<<<(E_EDGES + 255) / 256, 256>>>(ei, mask);

    dim3 g1((N_NODES + 127) / 128, HID / 128);
    k_gemm1<<<g1, 256>>>(x, w1, b1);          // <- profiled slot

    k_dis<<<(N_NODES + 255) / 256, 256>>>();
    k_scan1<<<NBLK, SCAN_B>>>();
    k_scan2<<<1, 128>>>();
    k_scan3<<<NBLK, SCAN_B>>>();
    k_fill<<<(TOT_E + 255) / 256, 256>>>(ei, mask);

    // 10 label-propagation steps (warp per node, pull mode, fp16 buffers)
    int plp_blocks = (N_NODES * 32 + 255) / 256;
    for (int s = 1; s <= 10; ++s)
        k_plp<<<plp_blocks, 256>>>(linit, mask, hard, s);

    // FC2 + combine (reads g_B0h = plp after step 10)
    k_final<<<(N_NODES + 7) / 8, 320>>>(w2, b2, alpha, out);
}